// round 1
// baseline (speedup 1.0000x reference)
#include <cuda_runtime.h>
#include <cuda_bf16.h>
#include <math.h>

// Problem constants
#define NPTS   16384      // 16*32*32
#define NCODES 8192
#define DIM    512
#define DIM4   (DIM/4)    // 128 float4 per row

// Tiling for fused distance+argmin kernel
#define BM 128
#define BK 128
#define BD 16

// Scratch (device globals: no allocation allowed)
__device__ int   g_idx[NPTS];
__device__ float g_cnorm[NCODES];
__device__ int   g_hist[NCODES];
__device__ float g_loss[1];

// ---------------------------------------------------------------------------
// init: zero histogram + loss accumulator (required each replay)
// ---------------------------------------------------------------------------
__global__ void vq_init_kernel() {
    int i = blockIdx.x * blockDim.x + threadIdx.x;
    if (i < NCODES) g_hist[i] = 0;
    if (i == 0) g_loss[0] = 0.0f;
}

// ---------------------------------------------------------------------------
// cnorm: ||c_k||^2 for every codebook row. One warp per row.
// ---------------------------------------------------------------------------
__global__ void vq_cnorm_kernel(const float* __restrict__ cb) {
    int row  = blockIdx.x * 8 + (threadIdx.x >> 5);
    int lane = threadIdx.x & 31;
    const float4* r = reinterpret_cast<const float4*>(cb + (size_t)row * DIM);
    float s = 0.0f;
#pragma unroll
    for (int i = lane; i < DIM4; i += 32) {
        float4 v = r[i];
        s += v.x * v.x + v.y * v.y + v.z * v.z + v.w * v.w;
    }
#pragma unroll
    for (int off = 16; off > 0; off >>= 1)
        s += __shfl_xor_sync(0xFFFFFFFFu, s, off);
    if (lane == 0) g_cnorm[row] = s;
}

// ---------------------------------------------------------------------------
// Fused distance + argmin.
// Block: 256 threads (16x16), computes BM=128 points vs all 8192 codes.
// For each BK=128 code tile: accumulate full-D dot products via register-
// blocked SGEMM (8x8 micro-tile), then score s = ||c||^2 - 2*dot and update
// running per-point (min, argmin). ||x||^2 is a per-point constant -> dropped.
// ---------------------------------------------------------------------------
__global__ __launch_bounds__(256)
void vq_argmin_kernel(const float* __restrict__ A,    // z_e   [NPTS, DIM]
                      const float* __restrict__ B) {  // codes [NCODES, DIM]
    __shared__ float sA[BD][BM];
    __shared__ float sB[BD][BK];
    __shared__ float rv[BM][16];
    __shared__ int   ri[BM][16];

    const int tid = threadIdx.x;
    const int tx = tid & 15;          // code stripe
    const int ty = tid >> 4;          // point stripe
    const int rowBase = blockIdx.x * BM;

    const float4* A4 = reinterpret_cast<const float4*>(A);
    const float4* B4 = reinterpret_cast<const float4*>(B);

    float bestv[8];
    int   besti[8];
#pragma unroll
    for (int i = 0; i < 8; i++) { bestv[i] = 3.4e38f; besti[i] = 0; }

    for (int k0 = 0; k0 < NCODES; k0 += BK) {
        float acc[8][8];
#pragma unroll
        for (int i = 0; i < 8; i++)
#pragma unroll
            for (int j = 0; j < 8; j++) acc[i][j] = 0.0f;

        for (int d0 = 0; d0 < DIM; d0 += BD) {
            // Stage A tile [BM x BD] and B tile [BK x BD] transposed (d-major).
            // 512 float4 slots each; 2 per thread.
#pragma unroll
            for (int i = 0; i < 2; i++) {
                int s  = tid * 2 + i;      // 0..511
                int m  = s >> 2;           // tile row
                int c4 = s & 3;            // float4 within 16-wide chunk
                float4 va = A4[(size_t)(rowBase + m) * DIM4 + (d0 >> 2) + c4];
                sA[c4 * 4 + 0][m] = va.x; sA[c4 * 4 + 1][m] = va.y;
                sA[c4 * 4 + 2][m] = va.z; sA[c4 * 4 + 3][m] = va.w;
                float4 vb = B4[(size_t)(k0 + m) * DIM4 + (d0 >> 2) + c4];
                sB[c4 * 4 + 0][m] = vb.x; sB[c4 * 4 + 1][m] = vb.y;
                sB[c4 * 4 + 2][m] = vb.z; sB[c4 * 4 + 3][m] = vb.w;
            }
            __syncthreads();

#pragma unroll
            for (int d = 0; d < BD; d++) {
                float4 a0 = *reinterpret_cast<const float4*>(&sA[d][ty * 8]);
                float4 a1 = *reinterpret_cast<const float4*>(&sA[d][ty * 8 + 4]);
                float4 b0 = *reinterpret_cast<const float4*>(&sB[d][tx * 8]);
                float4 b1 = *reinterpret_cast<const float4*>(&sB[d][tx * 8 + 4]);
                float ar[8] = {a0.x, a0.y, a0.z, a0.w, a1.x, a1.y, a1.z, a1.w};
                float br[8] = {b0.x, b0.y, b0.z, b0.w, b1.x, b1.y, b1.z, b1.w};
#pragma unroll
                for (int i = 0; i < 8; i++)
#pragma unroll
                    for (int j = 0; j < 8; j++)
                        acc[i][j] = fmaf(ar[i], br[j], acc[i][j]);
            }
            __syncthreads();
        }

        // Score this code tile and update running argmin.
#pragma unroll
        for (int j = 0; j < 8; j++) {
            int k = k0 + tx * 8 + j;
            float cn = __ldg(&g_cnorm[k]);
#pragma unroll
            for (int i = 0; i < 8; i++) {
                float s = cn - 2.0f * acc[i][j];
                if (s < bestv[i]) { bestv[i] = s; besti[i] = k; }
            }
        }
    }

    // Cross-column (tx) reduction to a single argmin per point.
#pragma unroll
    for (int i = 0; i < 8; i++) {
        rv[ty * 8 + i][tx] = bestv[i];
        ri[ty * 8 + i][tx] = besti[i];
    }
    __syncthreads();
    if (tid < BM) {
        float bv = rv[tid][0];
        int   bi = ri[tid][0];
#pragma unroll
        for (int t = 1; t < 16; t++) {
            float v = rv[tid][t];
            int   ix = ri[tid][t];
            if (v < bv || (v == bv && ix < bi)) { bv = v; bi = ix; }
        }
        g_idx[rowBase + tid] = bi;
    }
}

// ---------------------------------------------------------------------------
// Gather z_q, write idx-as-float, accumulate SSE + histogram.
// One block (128 threads) per point.
// ---------------------------------------------------------------------------
__global__ void vq_gather_kernel(const float* __restrict__ z,
                                 const float* __restrict__ cb,
                                 float* __restrict__ out_zq,
                                 float* __restrict__ out_idx) {
    __shared__ float warp_s[4];
    const int n = blockIdx.x;
    const int k = g_idx[n];
    const float4* c = reinterpret_cast<const float4*>(cb + (size_t)k * DIM);
    const float4* x = reinterpret_cast<const float4*>(z  + (size_t)n * DIM);
    float4* o = reinterpret_cast<float4*>(out_zq + (size_t)n * DIM);

    int i = threadIdx.x;               // 128 threads * 1 float4 each
    float4 cv = c[i], xv = x[i];
    o[i] = cv;
    float dx = cv.x - xv.x, dy = cv.y - xv.y, dz = cv.z - xv.z, dw = cv.w - xv.w;
    float ls = dx * dx + dy * dy + dz * dz + dw * dw;

#pragma unroll
    for (int off = 16; off > 0; off >>= 1)
        ls += __shfl_xor_sync(0xFFFFFFFFu, ls, off);
    int lane = threadIdx.x & 31, wid = threadIdx.x >> 5;
    if (lane == 0) warp_s[wid] = ls;
    __syncthreads();
    if (threadIdx.x == 0) {
        float t = warp_s[0] + warp_s[1] + warp_s[2] + warp_s[3];
        atomicAdd(&g_loss[0], t);
        atomicAdd(&g_hist[k], 1);
        out_idx[n] = (float)k;
    }
}

// ---------------------------------------------------------------------------
// Finalize: losses (identical forward values) + perplexity.
// ---------------------------------------------------------------------------
__global__ void vq_finalize_kernel(float* __restrict__ out3) {
    __shared__ float warp_s[8];
    float s = 0.0f;
    for (int i = threadIdx.x; i < NCODES; i += 256) {
        float p = (float)g_hist[i] * (1.0f / (float)NPTS);
        s += p * logf(p + 1e-10f);
    }
#pragma unroll
    for (int off = 16; off > 0; off >>= 1)
        s += __shfl_xor_sync(0xFFFFFFFFu, s, off);
    int lane = threadIdx.x & 31, wid = threadIdx.x >> 5;
    if (lane == 0) warp_s[wid] = s;
    __syncthreads();
    if (threadIdx.x == 0) {
        float H = 0.0f;
#pragma unroll
        for (int w = 0; w < 8; w++) H += warp_s[w];
        float L = g_loss[0] * (1.0f / ((float)NPTS * (float)DIM));
        out3[0] = L;            // commitment_loss (stop_grad doesn't change value)
        out3[1] = L;            // codebook_loss   (same forward value)
        out3[2] = expf(-H);     // perplexity
    }
}

// ---------------------------------------------------------------------------
extern "C" void kernel_launch(void* const* d_in, const int* in_sizes, int n_in,
                              void* d_out, int out_size) {
    const float* z  = (const float*)d_in[0];   // z_e      [16,32,32,512]
    const float* cb = (const float*)d_in[1];   // codebook [8192,512]
    float* out = (float*)d_out;

    float* out_zq   = out;                        // 8388608 floats
    float* out_idx  = out + (size_t)NPTS * DIM;   // 16384 floats
    float* out_scal = out_idx + NPTS;             // 3 floats

    vq_init_kernel<<<32, 256>>>();
    vq_cnorm_kernel<<<NCODES / 8, 256>>>(cb);
    vq_argmin_kernel<<<NPTS / BM, 256>>>(z, cb);
    vq_gather_kernel<<<NPTS, 128>>>(z, cb, out_zq, out_idx);
    vq_finalize_kernel<<<1, 256>>>(out_scal);
}

// round 4
// speedup vs baseline: 5.7536x; 5.7536x over previous
#include <cuda_runtime.h>
#include <cuda_fp16.h>
#include <math.h>
#include <stdint.h>

// Problem constants
#define NPTS   16384
#define NCODES 8192
#define DIM    512

// GEMM tiling
#define BM 128
#define BN 128
#define BKH 32              // k halves per tile
#define NKT (DIM / BKH)     // 16 k-tiles
#define PAD 40              // padded halves per smem row (conflict-free)
#define STAGE_BYTES (128 * PAD * 2)

#define CAP 128             // candidate list capacity per point
#define MARGIN 0.03f

// Scratch (device globals; no allocation allowed)
__device__ float    g_cnorm[NCODES];
__device__ int      g_hist[NCODES];
__device__ float    g_loss[1];
__device__ __half   g_Ah[(size_t)NPTS * DIM];
__device__ __half   g_Bh[(size_t)NCODES * DIM];
__device__ int      g_cnt[NPTS];
__device__ uint32_t g_cand[(size_t)NPTS * CAP];

// ---------------------------------------------------------------------------
// PTX helpers (baseline compute_103 features only: sm_80-era)
// ---------------------------------------------------------------------------
__device__ __forceinline__ uint32_t smem_to_u32(const void* p) {
    uint32_t a;
    asm("{ .reg .u64 t; cvta.to.shared.u64 t, %1; cvt.u32.u64 %0, t; }" : "=r"(a) : "l"(p));
    return a;
}
__device__ __forceinline__ void cp_async16(uint32_t dst, const void* src) {
    asm volatile("cp.async.cg.shared.global [%0], [%1], 16;" :: "r"(dst), "l"(src) : "memory");
}
__device__ __forceinline__ void ldm4(uint32_t* r, uint32_t addr) {
    asm volatile("ldmatrix.sync.aligned.m8n8.x4.shared.b16 {%0,%1,%2,%3}, [%4];"
        : "=r"(r[0]), "=r"(r[1]), "=r"(r[2]), "=r"(r[3]) : "r"(addr));
}
__device__ __forceinline__ void mma16816(float* c, const uint32_t* a, const uint32_t* b) {
    asm volatile("mma.sync.aligned.m16n8k16.row.col.f32.f16.f16.f32 "
        "{%0,%1,%2,%3}, {%4,%5,%6,%7}, {%8,%9}, {%0,%1,%2,%3};"
        : "+f"(c[0]), "+f"(c[1]), "+f"(c[2]), "+f"(c[3])
        : "r"(a[0]), "r"(a[1]), "r"(a[2]), "r"(a[3]), "r"(b[0]), "r"(b[1]));
}

// ---------------------------------------------------------------------------
// init: zero hist, loss, candidate counters
// ---------------------------------------------------------------------------
__global__ void vq_init_kernel() {
    int i = blockIdx.x * blockDim.x + threadIdx.x;
    if (i < NCODES) g_hist[i] = 0;
    if (i < NPTS)   g_cnt[i] = 0;
    if (i == 0)     g_loss[0] = 0.0f;
}

// ---------------------------------------------------------------------------
// cnorm: ||c_k||^2. One warp per row.
// ---------------------------------------------------------------------------
__global__ void vq_cnorm_kernel(const float* __restrict__ cb) {
    int row  = blockIdx.x * 8 + (threadIdx.x >> 5);
    int lane = threadIdx.x & 31;
    const float4* r = reinterpret_cast<const float4*>(cb + (size_t)row * DIM);
    float s = 0.0f;
#pragma unroll
    for (int i = lane; i < DIM / 4; i += 32) {
        float4 v = r[i];
        s += v.x * v.x + v.y * v.y + v.z * v.z + v.w * v.w;
    }
#pragma unroll
    for (int off = 16; off > 0; off >>= 1)
        s += __shfl_xor_sync(0xFFFFFFFFu, s, off);
    if (lane == 0) g_cnorm[row] = s;
}

// ---------------------------------------------------------------------------
// convert fp32 -> fp16 into device globals (NO host-side symbol addresses)
// ---------------------------------------------------------------------------
__global__ void vq_cvtA_kernel(const float4* __restrict__ src) {
    int i = blockIdx.x * blockDim.x + threadIdx.x;   // over NPTS*DIM/4
    float4 v = src[i];
    __half2* dst = reinterpret_cast<__half2*>(g_Ah);
    dst[2 * i + 0] = __floats2half2_rn(v.x, v.y);
    dst[2 * i + 1] = __floats2half2_rn(v.z, v.w);
}
__global__ void vq_cvtB_kernel(const float4* __restrict__ src) {
    int i = blockIdx.x * blockDim.x + threadIdx.x;   // over NCODES*DIM/4
    float4 v = src[i];
    __half2* dst = reinterpret_cast<__half2*>(g_Bh);
    dst[2 * i + 0] = __floats2half2_rn(v.x, v.y);
    dst[2 * i + 1] = __floats2half2_rn(v.z, v.w);
}

// ---------------------------------------------------------------------------
// Pass 1: fp16 mma.sync GEMM (points x codes dots) fused with per-row
// local-min + margin candidate push. 256 threads, warp grid 4(m) x 2(n),
// warp tile 32x64, double-buffered smem via cp.async, ldmatrix fragments.
// ---------------------------------------------------------------------------
__global__ void __launch_bounds__(256, 2)
vq_gemm_kernel() {
    __shared__ __align__(16) char smA[2 * STAGE_BYTES];
    __shared__ __align__(16) char smB[2 * STAGE_BYTES];
    __shared__ float sh_rmin[BM][2];

    const int tid  = threadIdx.x;
    const int lane = tid & 31;
    const int wid  = tid >> 5;
    const int wm   = wid & 3;        // 4 warps along m (32 rows each)
    const int wn   = wid >> 2;       // 2 warps along n (64 cols each)
    const int rowBase = blockIdx.y * BM;
    const int colBase = blockIdx.x * BN;

    const uint32_t suA = smem_to_u32(smA);
    const uint32_t suB = smem_to_u32(smB);

    // ldmatrix lane address components
    const int grp = lane >> 3, lr = lane & 7;
    const uint32_t a_off = ((uint32_t)((wm * 32 + lr + ((grp & 1) ? 8 : 0)) * PAD
                                       + ((grp & 2) ? 8 : 0))) * 2u;
    const uint32_t b_off = ((uint32_t)((wn * 64 + lr + ((grp >= 2) ? 8 : 0)) * PAD
                                       + ((grp & 1) ? 8 : 0))) * 2u;

    float acc[2][8][4];
#pragma unroll
    for (int mi = 0; mi < 2; mi++)
#pragma unroll
        for (int ni = 0; ni < 8; ni++)
#pragma unroll
            for (int c = 0; c < 4; c++) acc[mi][ni][c] = 0.0f;

    // tile loader: 2 chunks of 16B per thread per matrix
#define LOAD_TILE(s, kt) do {                                                        \
    _Pragma("unroll")                                                                \
    for (int t = 0; t < 2; t++) {                                                    \
        int ch = tid * 2 + t, r = ch >> 2, q = ch & 3;                               \
        uint32_t doff = (uint32_t)(s) * STAGE_BYTES + (uint32_t)(r * PAD + q * 8) * 2u; \
        cp_async16(suA + doff, g_Ah + (size_t)(rowBase + r) * DIM + (kt) * BKH + q * 8); \
        cp_async16(suB + doff, g_Bh + (size_t)(colBase + r) * DIM + (kt) * BKH + q * 8); \
    }                                                                                \
    asm volatile("cp.async.commit_group;" ::: "memory");                             \
} while (0)

    LOAD_TILE(0, 0);

    for (int kt = 0; kt < NKT; kt++) {
        const int s = kt & 1;
        if (kt < NKT - 1) {
            LOAD_TILE(s ^ 1, kt + 1);
            asm volatile("cp.async.wait_group 1;" ::: "memory");
        } else {
            asm volatile("cp.async.wait_group 0;" ::: "memory");
        }
        __syncthreads();

        const uint32_t stA = suA + (uint32_t)s * STAGE_BYTES;
        const uint32_t stB = suB + (uint32_t)s * STAGE_BYTES;
#pragma unroll
        for (int kk = 0; kk < 2; kk++) {
            uint32_t af[2][4], bf[4][4];
#pragma unroll
            for (int mi = 0; mi < 2; mi++)
                ldm4(af[mi], stA + a_off + (uint32_t)(mi * 16 * PAD * 2 + kk * 32));
#pragma unroll
            for (int n2 = 0; n2 < 4; n2++)
                ldm4(bf[n2], stB + b_off + (uint32_t)(n2 * 16 * PAD * 2 + kk * 32));
#pragma unroll
            for (int mi = 0; mi < 2; mi++)
#pragma unroll
                for (int n2 = 0; n2 < 4; n2++) {
                    uint32_t b01[2] = {bf[n2][0], bf[n2][1]};
                    uint32_t b23[2] = {bf[n2][2], bf[n2][3]};
                    mma16816(acc[mi][2 * n2 + 0], af[mi], b01);
                    mma16816(acc[mi][2 * n2 + 1], af[mi], b23);
                }
        }
        __syncthreads();
    }

    // ---- epilogue: scores, per-row local min, margin push ----
    const int qcol = (lane & 3) * 2;   // col pair within n8
    const int g    = lane >> 2;        // row within 8-group

    // overwrite acc with score s = ||c||^2 - 2*dot
#pragma unroll
    for (int mi = 0; mi < 2; mi++)
#pragma unroll
        for (int ni = 0; ni < 8; ni++) {
            int n_g = colBase + wn * 64 + ni * 8 + qcol;
            float cn0 = __ldg(&g_cnorm[n_g]);
            float cn1 = __ldg(&g_cnorm[n_g + 1]);
            acc[mi][ni][0] = cn0 - 2.0f * acc[mi][ni][0];
            acc[mi][ni][1] = cn1 - 2.0f * acc[mi][ni][1];
            acc[mi][ni][2] = cn0 - 2.0f * acc[mi][ni][2];
            acc[mi][ni][3] = cn1 - 2.0f * acc[mi][ni][3];
        }

    // per-row (within-warp) min: 16 values per lane, then quad reduce
#pragma unroll
    for (int mi = 0; mi < 2; mi++)
#pragma unroll
        for (int h = 0; h < 2; h++) {
            float mv = 3.4e38f;
#pragma unroll
            for (int ni = 0; ni < 8; ni++) {
                mv = fminf(mv, acc[mi][ni][h * 2 + 0]);
                mv = fminf(mv, acc[mi][ni][h * 2 + 1]);
            }
            mv = fminf(mv, __shfl_xor_sync(0xFFFFFFFFu, mv, 1));
            mv = fminf(mv, __shfl_xor_sync(0xFFFFFFFFu, mv, 2));
            if ((lane & 3) == 0)
                sh_rmin[wm * 32 + mi * 16 + h * 8 + g][wn] = mv;
        }
    __syncthreads();

    // push candidates within margin of CTA-local row min
#pragma unroll
    for (int mi = 0; mi < 2; mi++)
#pragma unroll
        for (int h = 0; h < 2; h++) {
            int r = wm * 32 + mi * 16 + h * 8 + g;
            float thr = fminf(sh_rmin[r][0], sh_rmin[r][1]) + MARGIN;
            int grow = rowBase + r;
#pragma unroll
            for (int ni = 0; ni < 8; ni++) {
#pragma unroll
                for (int cc = 0; cc < 2; cc++) {
                    float sv = acc[mi][ni][h * 2 + cc];
                    if (sv <= thr) {
                        int col = colBase + wn * 64 + ni * 8 + qcol + cc;
                        int pos = atomicAdd(&g_cnt[grow], 1);
                        if (pos < CAP) {
                            uint32_t hs = (uint32_t)__half_as_ushort(__float2half_rn(sv));
                            g_cand[(size_t)grow * CAP + pos] = (hs << 16) | (uint32_t)col;
                        }
                    }
                }
            }
        }
}

// ---------------------------------------------------------------------------
// Pass 2: per point — min over candidate list, exact fp32 rescore of those
// within margin, pick argmin; fused gather + loss + histogram.
// ---------------------------------------------------------------------------
__global__ void __launch_bounds__(256)
vq_select_kernel(const float* __restrict__ z,
                 const float* __restrict__ cb,
                 float* __restrict__ out_zq,
                 float* __restrict__ out_idx) {
    __shared__ float    sh_minv;
    __shared__ int      sh_ecnt;
    __shared__ int      sh_eidx[32];
    __shared__ float    sh_ev[32];
    __shared__ float    sh_sse[8];
    __shared__ int      sh_best;

    const int n    = blockIdx.x;
    const int tid  = threadIdx.x;
    const int lane = tid & 31;
    const int wid  = tid >> 5;

    int cnt = g_cnt[n];
    if (cnt > CAP) cnt = CAP;
    const uint32_t* cand = g_cand + (size_t)n * CAP;

    if (tid == 0) sh_ecnt = 0;

    // warp 0: min of approx scores
    if (wid == 0) {
        float mv = 3.4e38f;
        for (int i = lane; i < cnt; i += 32) {
            float v = __half2float(__ushort_as_half((unsigned short)(cand[i] >> 16)));
            mv = fminf(mv, v);
        }
#pragma unroll
        for (int off = 16; off > 0; off >>= 1)
            mv = fminf(mv, __shfl_xor_sync(0xFFFFFFFFu, mv, off));
        if (lane == 0) sh_minv = mv;
    }
    __syncthreads();

    // build exact-rescore list: anything within margin of the observed min
    float thr = sh_minv + MARGIN;
    if (tid < cnt) {
        uint32_t p = cand[tid];
        float v = __half2float(__ushort_as_half((unsigned short)(p >> 16)));
        if (v <= thr) {
            int pos = atomicAdd(&sh_ecnt, 1);
            if (pos < 32) sh_eidx[pos] = (int)(p & 0xFFFFu);
        }
    }
    __syncthreads();
    int ecnt = sh_ecnt;
    if (ecnt > 32) ecnt = 32;

    // exact fp32 rescore (one warp per candidate)
    for (int e = wid; e < ecnt; e += 8) {
        int k = sh_eidx[e];
        const float* xr = z  + (size_t)n * DIM;
        const float* cr = cb + (size_t)k * DIM;
        float dot = 0.0f;
#pragma unroll
        for (int d = lane; d < DIM; d += 32)
            dot = fmaf(xr[d], cr[d], dot);
#pragma unroll
        for (int off = 16; off > 0; off >>= 1)
            dot += __shfl_xor_sync(0xFFFFFFFFu, dot, off);
        if (lane == 0) sh_ev[e] = __ldg(&g_cnorm[k]) - 2.0f * dot;
    }
    __syncthreads();

    if (tid == 0) {
        float bv = 3.4e38f;
        int   bi = NCODES;
        for (int e = 0; e < ecnt; e++) {
            float v = sh_ev[e];
            int   k = sh_eidx[e];
            if (v < bv || (v == bv && k < bi)) { bv = v; bi = k; }
        }
        sh_best = bi;
    }
    __syncthreads();

    // fused gather + loss + hist
    const int best = sh_best;
    const float2* c2 = reinterpret_cast<const float2*>(cb + (size_t)best * DIM);
    const float2* x2 = reinterpret_cast<const float2*>(z  + (size_t)n * DIM);
    float2* o2 = reinterpret_cast<float2*>(out_zq + (size_t)n * DIM);
    float2 cv = c2[tid], xv = x2[tid];
    o2[tid] = cv;
    float dx = cv.x - xv.x, dy = cv.y - xv.y;
    float ls = dx * dx + dy * dy;
#pragma unroll
    for (int off = 16; off > 0; off >>= 1)
        ls += __shfl_xor_sync(0xFFFFFFFFu, ls, off);
    if (lane == 0) sh_sse[wid] = ls;
    __syncthreads();
    if (tid == 0) {
        float t = 0.0f;
#pragma unroll
        for (int w = 0; w < 8; w++) t += sh_sse[w];
        atomicAdd(&g_loss[0], t);
        atomicAdd(&g_hist[best], 1);
        out_idx[n] = (float)best;
    }
}

// ---------------------------------------------------------------------------
// finalize: losses + perplexity
// ---------------------------------------------------------------------------
__global__ void vq_finalize_kernel(float* __restrict__ out3) {
    __shared__ float warp_s[8];
    float s = 0.0f;
    for (int i = threadIdx.x; i < NCODES; i += 256) {
        float p = (float)g_hist[i] * (1.0f / (float)NPTS);
        s += p * logf(p + 1e-10f);
    }
#pragma unroll
    for (int off = 16; off > 0; off >>= 1)
        s += __shfl_xor_sync(0xFFFFFFFFu, s, off);
    int lane = threadIdx.x & 31, wid = threadIdx.x >> 5;
    if (lane == 0) warp_s[wid] = s;
    __syncthreads();
    if (threadIdx.x == 0) {
        float H = 0.0f;
#pragma unroll
        for (int w = 0; w < 8; w++) H += warp_s[w];
        float L = g_loss[0] * (1.0f / ((float)NPTS * (float)DIM));
        out3[0] = L;            // commitment_loss
        out3[1] = L;            // codebook_loss
        out3[2] = expf(-H);     // perplexity
    }
}

// ---------------------------------------------------------------------------
extern "C" void kernel_launch(void* const* d_in, const int* in_sizes, int n_in,
                              void* d_out, int out_size) {
    const float* z  = (const float*)d_in[0];   // z_e      [16,32,32,512]
    const float* cb = (const float*)d_in[1];   // codebook [8192,512]
    float* out = (float*)d_out;

    float* out_zq   = out;
    float* out_idx  = out + (size_t)NPTS * DIM;
    float* out_scal = out_idx + NPTS;

    vq_init_kernel<<<64, 256>>>();
    vq_cnorm_kernel<<<NCODES / 8, 256>>>(cb);
    vq_cvtA_kernel<<<NPTS * DIM / 4 / 256, 256>>>((const float4*)z);
    vq_cvtB_kernel<<<NCODES * DIM / 4 / 256, 256>>>((const float4*)cb);
    {
        dim3 grid(NCODES / BN, NPTS / BM);
        vq_gemm_kernel<<<grid, 256>>>();
    }
    vq_select_kernel<<<NPTS, 256>>>(z, cb, out_zq, out_idx);
    vq_finalize_kernel<<<1, 256>>>(out_scal);
}